// round 15
// baseline (speedup 1.0000x reference)
#include <cuda_runtime.h>
#include <cuda_bf16.h>
#include <cstdint>
#include <math.h>

// ============================================================================
// Problem constants
// ============================================================================
#define HIDDEN   1024
#define BATCH    4096
#define M_TOTAL  16384          // BATCH * 4 pair rows
#define GCOLS    1024
#define KQ       3072
#define KZ       2048
#define BM       64             // rows per CTA
#define BG       64             // g-columns per CTA
#define NKT      48             // KQ / 64
#define NKT_Z    32             // KZ / 64
#define STAGE_BYTES 32768       // A 8KB + Bd 8KB + Bql 8KB + Bzl 8KB
#define OFF_BIAS (3 * STAGE_BYTES)          // 98304
#define OFF_RED  (OFF_BIAS + 768)
#define SMEM_USE (OFF_RED + 128)
#define SMEM_REQ (SMEM_USE + 1024)          // slack for manual 1KB align
#define SL_BLOCKS 32
#define EV_ROWS  (BATCH * 5)    // 20480
#define CX_ROWS  (BATCH * 4)    // 16384

// ============================================================================
// Scratch (__device__ globals; no allocation allowed)
// ============================================================================
__device__ __align__(128) __nv_bfloat16 g_ev[(size_t)EV_ROWS * HIDDEN]; // 42 MB
__device__ __align__(128) __nv_bfloat16 g_cx[(size_t)CX_ROWS * HIDDEN]; // 34 MB
__device__ __align__(128) __nv_bfloat16 g_Wd [(size_t)GCOLS * KQ];      // 6 MB  [g][k]
__device__ __align__(128) __nv_bfloat16 g_Wzl[(size_t)GCOLS * KZ];      // 4 MB
__device__ __align__(128) __nv_bfloat16 g_Wql[(size_t)GCOLS * KQ];      // 6 MB
__device__ float g_kl_partial[4096];
__device__ float g_small_partial[SL_BLOCKS * 4];

// ============================================================================
// PTX helpers (baseline sm_100 ISA only: cp.async, ldmatrix, mma.sync)
// ============================================================================
__device__ __forceinline__ uint32_t smem_to_u32(const void* p) {
    uint32_t a;
    asm("{ .reg .u64 t; cvta.to.shared.u64 t, %1; cvt.u32.u64 %0, t; }" : "=r"(a) : "l"(p));
    return a;
}
__device__ __forceinline__ void cp16(uint32_t dst, const void* src) {
    asm volatile("cp.async.cg.shared.global [%0], [%1], 16;" :: "r"(dst), "l"(src) : "memory");
}
#define CP_COMMIT() asm volatile("cp.async.commit_group;" ::: "memory")

#define LDSM4(r, addr) \
    asm volatile("ldmatrix.sync.aligned.m8n8.x4.shared.b16 {%0,%1,%2,%3}, [%4];" \
        : "=r"((r)[0]), "=r"((r)[1]), "=r"((r)[2]), "=r"((r)[3]) : "r"(addr))

#define MMA16816(c, a, b0, b1) \
    asm volatile("mma.sync.aligned.m16n8k16.row.col.f32.bf16.bf16.f32 " \
        "{%0,%1,%2,%3}, {%4,%5,%6,%7}, {%8,%9}, {%0,%1,%2,%3};" \
        : "+f"((c)[0]), "+f"((c)[1]), "+f"((c)[2]), "+f"((c)[3]) \
        : "r"((a)[0]), "r"((a)[1]), "r"((a)[2]), "r"((a)[3]), \
          "r"(b0), "r"(b1))

// ============================================================================
// Prep 1: elementwise fp32 -> bf16 of events and contexts (no concatenation)
// ============================================================================
__global__ __launch_bounds__(256) void conv_kernel(
    const float* __restrict__ events, const float* __restrict__ contexts) {
    const int r = blockIdx.x;                 // 0..EV_ROWS+CX_ROWS-1
    const float* src;
    __nv_bfloat162* dst;
    if (r < EV_ROWS) {
        src = events + (size_t)r * HIDDEN;
        dst = (__nv_bfloat162*)(g_ev + (size_t)r * HIDDEN);
    } else {
        const int rc = r - EV_ROWS;
        src = contexts + (size_t)rc * HIDDEN;
        dst = (__nv_bfloat162*)(g_cx + (size_t)rc * HIDDEN);
    }
    const int t = threadIdx.x;                // 256 threads x float4 = 1024
    float4 v = ((const float4*)src)[t];
    dst[t * 2 + 0] = __floats2bfloat162_rn(v.x, v.y);
    dst[t * 2 + 1] = __floats2bfloat162_rn(v.z, v.w);
}

// ============================================================================
// Prep 2: transposed bf16 weights
//   g_Wd [g][k] = (k<2048 ? Wz[k][g] : 0) - Wqz[k][g]   (k<3072)
//   g_Wzl[g][k] = Wv[k][g]                              (k<2048)
//   g_Wql[g][k] = Wqv[k][g]                             (k<3072)
// ============================================================================
__global__ void transpose_w_kernel(
    const float* __restrict__ Wz, const float* __restrict__ Wqz,
    const float* __restrict__ Wv, const float* __restrict__ Wqv) {
    __shared__ float tile[32][33];
    const int which = blockIdx.z;            // 0=d, 1=zl, 2=ql
    const int k0 = blockIdx.x * 32, g0 = blockIdx.y * 32;
    if (which == 1 && k0 >= KZ) return;
    const int tx = threadIdx.x, ty = threadIdx.y;
    for (int i = ty; i < 32; i += 8) {
        const int k = k0 + i;
        float v;
        if (which == 0)
            v = ((k < KZ) ? Wz[(size_t)k * GCOLS + g0 + tx] : 0.f)
                - Wqz[(size_t)k * GCOLS + g0 + tx];
        else if (which == 1)
            v = Wv[(size_t)k * GCOLS + g0 + tx];
        else
            v = Wqv[(size_t)k * GCOLS + g0 + tx];
        tile[i][tx] = v;
    }
    __syncthreads();
    for (int i = ty; i < 32; i += 8) {
        const __nv_bfloat16 b = __float2bfloat16(tile[tx][i]);
        if (which == 0)      g_Wd [(size_t)(g0 + i) * KQ + k0 + tx] = b;
        else if (which == 1) g_Wzl[(size_t)(g0 + i) * KZ + k0 + tx] = b;
        else                 g_Wql[(size_t)(g0 + i) * KQ + k0 + tx] = b;
    }
}

// ============================================================================
// No-op kernel keeps gemm_kl_kernel at ncu capture slot 5
// ============================================================================
__global__ void dummy_kernel() {}

// ============================================================================
// Fused triple-GEMM + KL epilogue (mma.sync bf16).
// grid (16 g-blocks, 256 m-tiles), 128 threads = 4 warps (1/SMSP), 2 CTAs/SM.
// A loaded directly from g_ev/g_cx per k-segment ([e_s|e_{s+1}] contiguous).
// Stage loads split into quarters interleaved with the MMA ladder.
// ============================================================================
__global__ __launch_bounds__(128, 2) void gemm_kl_kernel(
    const float* __restrict__ bz, const float* __restrict__ bqz,
    const float* __restrict__ bv, const float* __restrict__ bqv) {
    extern __shared__ char dsm[];
    const uint32_t raw = smem_to_u32(dsm);
    const uint32_t sb = (raw + 1023u) & ~1023u;
    char* smc = dsm + (sb - raw);
    const int tid = threadIdx.x;
    const int lane = tid & 31;
    const int wid = tid >> 5;              // 0..3 == SMSP
    const int nb0 = blockIdx.x * BG;
    const int m0 = blockIdx.y * BM;

    float* sBD = (float*)(smc + OFF_BIAS);        // 64
    float* sBZL = sBD + 64;                       // 64
    float* sBQL = sBZL + 64;                      // 64
    if (tid < 64) {
        sBD[tid]  = bz[nb0 + tid] - bqz[nb0 + tid];
        sBZL[tid] = bv[nb0 + tid];
        sBQL[tid] = bqv[nb0 + tid];
    }

    // ---- per-lane ldmatrix address components (xor swizzle) ----
    const int wn = wid;              // 4 warps along N (16 cols each)
    const uint32_t aswz = (uint32_t)(lane & 7) * 16u;
    const uint32_t acb = (uint32_t)(lane >> 4) * 16u;
    uint32_t aoff[4];
#pragma unroll
    for (int p = 0; p < 4; p++)
        aoff[p] = (uint32_t)(p * 16 + (lane & 15)) * 128u;
    const int brr = wn * 16 + ((lane >> 4) << 3) + (lane & 7);
    const uint32_t boff = (uint32_t)brr * 128u;
    const uint32_t bswz = (uint32_t)(lane & 7) * 16u;
    const uint32_t bcb = (uint32_t)((lane >> 3) & 1) * 16u;

    // ---- accumulators ----
    float accD[4][2][4], accZL[4][2][4], accQL[4][2][4];
#pragma unroll
    for (int p = 0; p < 4; p++)
#pragma unroll
        for (int h = 0; h < 2; h++)
#pragma unroll
            for (int c = 0; c < 4; c++) {
                accD[p][h][c] = 0.f; accZL[p][h][c] = 0.f; accQL[p][h][c] = 0.f;
            }

    // ---- loader addressing: row0 = tid>>3 (+16 per j), cb fixed ----
    const int row0 = tid >> 3;
    const int cb16 = (tid & 7) * 16;
    const uint32_t dst0 = (uint32_t)(row0 * 128 + cb16) ^ ((uint32_t)(row0 & 7) * 16u);
    // A: r = m0+row0 (+16 per j -> ev idx +20 rows, cx idx +16 rows: linear)
    const int r0 = m0 + row0;
    const int ii = r0 >> 2, ss = r0 & 3;
    const char* pA = (const char*)(g_ev + ((size_t)ii * 5 + ss) * HIDDEN) + cb16;
    const char* pC = (const char*)(g_cx + ((size_t)ii * 4 + ss) * HIDDEN) + cb16 - 4096;
    const char* pBd  = (const char*)(g_Wd  + (size_t)(nb0 + row0) * KQ) + cb16;
    const char* pBql = (const char*)(g_Wql + (size_t)(nb0 + row0) * KQ) + cb16;
    const char* pBzl = (const char*)(g_Wzl + (size_t)(nb0 + row0) * KZ) + cb16;

#define QA(kt) do { \
        const uint32_t _b = sb + (uint32_t)((kt) % 3) * STAGE_BYTES + dst0; \
        const int _kb = (kt) * 128; \
        const char* _a = ((kt) < 32) ? (pA + _kb) : (pC + _kb); \
        const int _as = ((kt) < 32) ? 40960 : 32768; \
        _Pragma("unroll") \
        for (int _j = 0; _j < 4; _j++) cp16(_b + _j * 2048u, _a + _j * _as); \
    } while (0)
#define QD(kt) do { \
        const uint32_t _b = sb + (uint32_t)((kt) % 3) * STAGE_BYTES + 8192u + dst0; \
        const char* _s = pBd + (kt) * 128; \
        _Pragma("unroll") \
        for (int _j = 0; _j < 4; _j++) cp16(_b + _j * 2048u, _s + _j * 98304); \
    } while (0)
#define QQ(kt) do { \
        const uint32_t _b = sb + (uint32_t)((kt) % 3) * STAGE_BYTES + 16384u + dst0; \
        const char* _s = pBql + (kt) * 128; \
        _Pragma("unroll") \
        for (int _j = 0; _j < 4; _j++) cp16(_b + _j * 2048u, _s + _j * 98304); \
    } while (0)
#define QZ(kt) do { \
        if ((kt) < NKT_Z) { \
            const uint32_t _b = sb + (uint32_t)((kt) % 3) * STAGE_BYTES + 24576u + dst0; \
            const char* _s = pBzl + (kt) * 128; \
            _Pragma("unroll") \
            for (int _j = 0; _j < 4; _j++) cp16(_b + _j * 2048u, _s + _j * 65536); \
        } \
    } while (0)
#define LOAD_FULL(kt) do { QA(kt); QD(kt); QQ(kt); QZ(kt); CP_COMMIT(); } while (0)

    // ---- fragment double buffers ----
    uint32_t aF[2][4][4], fdF[2][4], fqlF[2][4], fzlF[2][4];

#define LDFRAG(buf, ks, stA, full) do { \
        const uint32_t _ka = (((uint32_t)(ks) * 32u + acb) ^ aswz); \
        const uint32_t _kb = (((uint32_t)(ks) * 32u + bcb) ^ bswz); \
        LDSM4(aF[buf][0], (stA) + aoff[0] + _ka); \
        LDSM4(aF[buf][1], (stA) + aoff[1] + _ka); \
        LDSM4(aF[buf][2], (stA) + aoff[2] + _ka); \
        LDSM4(aF[buf][3], (stA) + aoff[3] + _ka); \
        LDSM4(fdF[buf],  (stA) + 8192u + boff + _kb); \
        LDSM4(fqlF[buf], (stA) + 16384u + boff + _kb); \
        if (full) LDSM4(fzlF[buf], (stA) + 24576u + boff + _kb); \
    } while (0)

#define DOMMA(buf, full) do { \
        _Pragma("unroll") \
        for (int _p = 0; _p < 4; _p++) { \
            _Pragma("unroll") \
            for (int _h = 0; _h < 2; _h++) { \
                MMA16816(accD[_p][_h],  aF[buf][_p], fdF[buf][2*_h],  fdF[buf][2*_h+1]); \
                MMA16816(accQL[_p][_h], aF[buf][_p], fqlF[buf][2*_h], fqlF[buf][2*_h+1]); \
            } \
        } \
        if (full) { \
            _Pragma("unroll") \
            for (int _p = 0; _p < 4; _p++) { \
                _Pragma("unroll") \
                for (int _h = 0; _h < 2; _h++) \
                    MMA16816(accZL[_p][_h], aF[buf][_p], fzlF[buf][2*_h], fzlF[buf][2*_h+1]); \
            } \
        } \
    } while (0)

    // ---- prologue: 2 stages in flight, prefetch ks0 of stage 0 ----
    LOAD_FULL(0);
    LOAD_FULL(1);
    asm volatile("cp.async.wait_group 1;" ::: "memory");
    __syncthreads();
    LDFRAG(0, 0, sb, true);

    for (int kt = 0; kt < NKT; kt++) {
        const uint32_t stA = sb + (uint32_t)(kt % 3) * STAGE_BYTES;
        const bool full = (kt < NKT_Z);
        const bool doload = (kt + 2 < NKT);
        // buf0 already holds ks0 fragments (prefetched)
        LDFRAG(1, 1, stA, full);
        if (doload) QA(kt + 2);
        DOMMA(0, full);
        LDFRAG(0, 2, stA, full);
        if (doload) QD(kt + 2);
        DOMMA(1, full);
        LDFRAG(1, 3, stA, full);
        if (doload) { QQ(kt + 2); QZ(kt + 2); CP_COMMIT(); }
        DOMMA(0, full);
        if (kt < NKT - 1) {
            // stage kt+1 fully resident after this wait+barrier
            if (doload) { asm volatile("cp.async.wait_group 1;" ::: "memory"); }
            else        { asm volatile("cp.async.wait_group 0;" ::: "memory"); }
            __syncthreads();
            const uint32_t stN = sb + (uint32_t)((kt + 1) % 3) * STAGE_BYTES;
            const bool fulln = (kt + 1 < NKT_Z);
            LDFRAG(0, 0, stN, fulln);     // prefetch next kt's ks0
        }
        DOMMA(1, full);
    }

    // ---- fused KL epilogue: identical fragment layouts -> no shuffles ----
    float acckl = 0.f;
#pragma unroll
    for (int p = 0; p < 4; p++) {
#pragma unroll
        for (int h = 0; h < 2; h++) {
            const int col = wn * 16 + h * 8 + (lane & 3) * 2;
            const float bd0 = sBD[col], bd1 = sBD[col + 1];
            const float bl0 = sBZL[col], bl1 = sBZL[col + 1];
            const float bq0 = sBQL[col], bq1 = sBQL[col + 1];
#pragma unroll
            for (int rr = 0; rr < 2; rr++) {
                const float d0 = accD[p][h][2 * rr] + bd0;
                const float d1 = accD[p][h][2 * rr + 1] + bd1;
                const float zl0 = accZL[p][h][2 * rr] + bl0;
                const float zl1 = accZL[p][h][2 * rr + 1] + bl1;
                const float ql0 = accQL[p][h][2 * rr] + bq0;
                const float ql1 = accQL[p][h][2 * rr + 1] + bq1;
                acckl += ql0 - zl0 + (expf(zl0) + d0 * d0) * expf(-ql0) - 1.f;
                acckl += ql1 - zl1 + (expf(zl1) + d1 * d1) * expf(-ql1) - 1.f;
            }
        }
    }

    // deterministic reduction over 4 warps
#pragma unroll
    for (int s = 16; s > 0; s >>= 1)
        acckl += __shfl_down_sync(0xFFFFFFFFu, acckl, s);
    float* red = (float*)(smc + OFF_RED);
    if (lane == 0) red[wid] = acckl;
    __syncthreads();
    if (tid == 0) {
        float s = 0.f;
        for (int w = 0; w < 4; w++) s += red[w];
        g_kl_partial[blockIdx.y * 16 + blockIdx.x] = s;
    }
}

// ============================================================================
// Small losses: 32 blocks x 128 threads, one batch element each
// ============================================================================
__global__ __launch_bounds__(128) void small_loss_kernel(
    const float* __restrict__ ps, const float* __restrict__ pt,
    const float* __restrict__ pc, const int* __restrict__ labels,
    const int* __restrict__ scene, const int* __restrict__ thr) {
    __shared__ float red[128];
    const int b = blockIdx.x * 128 + threadIdx.x;    // < 4096
    float wce = 0.f, wsum = 0.f, tsum = 0.f, vsum = 0.f;
    {
        const int lab = labels[b];
        const int s = scene[b], t = thr[b];
        const bool l5 = (lab == 5), l2 = (lab == 2), l3 = (lab == 3);
        const bool le = !(l5 | l2 | l3);
        const int nv = l5 ? 3 : (l2 ? 1 : (l3 ? 2 : 3));
        const int last = nv - 1;
        const float* psb = ps + (size_t)b * 6;
        const float* ptb = pt + (size_t)b * 6;
        const float* pcb = pc + (size_t)b * 6;
        #pragma unroll
        for (int slot = 0; slot < 3; slot++) {
            if (slot >= nv) break;
            int chain = l5 ? 1 : (l2 ? 0 : (l3 ? (slot == 0 ? 1 : 0)
                                               : (slot == 2 ? 0 : 1)));
            int ps_col = (!l5 && slot == last) ? s : 0;
            int pt_row = (l3 && slot == 1) ? (t == 1 ? 0 : 1) : slot;
            int pt_col = (l2 && slot == 0) ? t : ((le && slot == 2) ? t : 0);
            int pcs_col = l5 ? 1 : (slot == last ? 0 : 1);
            float PS = psb[slot * 2 + ps_col];
            float PT = ptb[pt_row * 2 + pt_col];
            float PCS = pcb[slot * 2 + pcs_col];
            float a0 = pcb[slot * 2 + 0], a1 = pcb[slot * 2 + 1];
            float mx = fmaxf(a0, a1);
            float lse = mx + logf(expf(a0 - mx) + expf(a1 - mx));
            float logp = (chain == 0 ? a0 : a1) - lse;
            float w = (chain == 0) ? 0.6f : 0.4f;
            wce += -w * logp;
            wsum += w;
            float lsig = fminf(PCS, 0.f) - log1pf(expf(-fabsf(PCS)));
            tsum += fabsf(logf(PS) + logf(PT) - lsig);
            vsum += 1.f;
        }
    }
    const int tid = threadIdx.x;
    float vals[4] = {wce, wsum, tsum, vsum};
    for (int v = 0; v < 4; v++) {
        red[tid] = vals[v];
        __syncthreads();
        for (int sft = 64; sft > 0; sft >>= 1) {
            if (tid < sft) red[tid] += red[tid + sft];
            __syncthreads();
        }
        if (tid == 0) g_small_partial[blockIdx.x * 4 + v] = red[0];
        __syncthreads();
    }
}

// ============================================================================
// Final combine
// ============================================================================
__global__ __launch_bounds__(1024) void combine_kernel(float* __restrict__ out) {
    __shared__ float red[1024];
    float s = 0.f;
    for (int i = threadIdx.x; i < 4096; i += 1024) s += g_kl_partial[i];
    red[threadIdx.x] = s;
    __syncthreads();
    for (int sft = 512; sft > 0; sft >>= 1) {
        if (threadIdx.x < sft) red[threadIdx.x] += red[threadIdx.x + sft];
        __syncthreads();
    }
    if (threadIdx.x == 0) {
        float sm[4] = {0.f, 0.f, 0.f, 0.f};
        for (int bi = 0; bi < SL_BLOCKS; bi++)
            for (int v = 0; v < 4; v++) sm[v] += g_small_partial[bi * 4 + v];
        const float kl_loss = 0.5f * red[0] / (float)M_TOTAL;
        out[0] = sm[0] / sm[1] + kl_loss + sm[2] / sm[3];
    }
}

// ============================================================================
// kernel_launch
// ============================================================================
extern "C" void kernel_launch(void* const* d_in, const int* in_sizes, int n_in,
                              void* d_out, int out_size) {
    const float* events   = (const float*)d_in[0];
    const float* contexts = (const float*)d_in[1];
    const float* ps       = (const float*)d_in[2];
    const float* pt       = (const float*)d_in[3];
    const float* pc       = (const float*)d_in[4];
    const int*   labels   = (const int*)d_in[5];
    const int*   scene    = (const int*)d_in[6];
    const int*   thr      = (const int*)d_in[7];
    const float* Wz  = (const float*)d_in[8];
    const float* bz  = (const float*)d_in[9];
    const float* Wv  = (const float*)d_in[10];
    const float* bv  = (const float*)d_in[11];
    const float* Wqz = (const float*)d_in[12];
    const float* bqz = (const float*)d_in[13];
    const float* Wqv = (const float*)d_in[14];
    const float* bqv = (const float*)d_in[15];
    float* out = (float*)d_out;

    cudaFuncSetAttribute(gemm_kl_kernel,
                         cudaFuncAttributeMaxDynamicSharedMemorySize, SMEM_REQ);

    conv_kernel<<<EV_ROWS + CX_ROWS, 256>>>(events, contexts);                   // my #0
    transpose_w_kernel<<<dim3(KQ / 32, GCOLS / 32, 3), dim3(32, 8)>>>(Wz, Wqz, Wv, Wqv); // #1
    dummy_kernel<<<1, 32>>>();                                                   // #2
    gemm_kl_kernel<<<dim3(GCOLS / BG, M_TOTAL / BM), 128, SMEM_REQ>>>(bz, bqz, bv, bqv); // #3 <- ncu slot 5
    small_loss_kernel<<<SL_BLOCKS, 128>>>(ps, pt, pc, labels, scene, thr);       // #4
    combine_kernel<<<1, 1024>>>(out);                                            // #5
}

// round 16
// speedup vs baseline: 1.0825x; 1.0825x over previous
#include <cuda_runtime.h>
#include <cuda_bf16.h>
#include <cstdint>
#include <math.h>

// ============================================================================
// Problem constants
// ============================================================================
#define HIDDEN   1024
#define BATCH    4096
#define M_TOTAL  16384          // BATCH * 4 pair rows
#define GCOLS    1024
#define KQ       3072
#define KZ       2048
#define BM       64             // rows per CTA
#define BG       64             // g-columns per CTA
#define NKT      48             // KQ / 64
#define NKT_Z    32             // KZ / 64
#define STAGE_BYTES 32768       // A 8KB + Bd 8KB + Bql 8KB + Bzl 8KB
#define OFF_BIAS (3 * STAGE_BYTES)          // 98304
#define OFF_RED  (OFF_BIAS + 768)
#define SMEM_USE (OFF_RED + 128)
#define SMEM_REQ (SMEM_USE + 1024)          // slack for manual 1KB align
#define SL_BLOCKS 32
#define EV_ROWS  (BATCH * 5)    // 20480
#define CX_ROWS  (BATCH * 4)    // 16384

// ============================================================================
// Scratch (__device__ globals; no allocation allowed)
// ============================================================================
__device__ __align__(128) __nv_bfloat16 g_ev[(size_t)EV_ROWS * HIDDEN]; // 42 MB
__device__ __align__(128) __nv_bfloat16 g_cx[(size_t)CX_ROWS * HIDDEN]; // 34 MB
__device__ __align__(128) __nv_bfloat16 g_Wd [(size_t)GCOLS * KQ];      // 6 MB  [g][k]
__device__ __align__(128) __nv_bfloat16 g_Wzl[(size_t)GCOLS * KZ];      // 4 MB
__device__ __align__(128) __nv_bfloat16 g_Wql[(size_t)GCOLS * KQ];      // 6 MB
__device__ float g_kl_partial[4096];
__device__ float g_small_partial[SL_BLOCKS * 4];

// ============================================================================
// PTX helpers (baseline sm_100 ISA only: cp.async, ldmatrix, mma.sync)
// ============================================================================
__device__ __forceinline__ uint32_t smem_to_u32(const void* p) {
    uint32_t a;
    asm("{ .reg .u64 t; cvta.to.shared.u64 t, %1; cvt.u32.u64 %0, t; }" : "=r"(a) : "l"(p));
    return a;
}
__device__ __forceinline__ void cp16(uint32_t dst, const void* src) {
    asm volatile("cp.async.cg.shared.global [%0], [%1], 16;" :: "r"(dst), "l"(src) : "memory");
}
#define CP_COMMIT() asm volatile("cp.async.commit_group;" ::: "memory")

#define LDSM4(r, addr) \
    asm volatile("ldmatrix.sync.aligned.m8n8.x4.shared.b16 {%0,%1,%2,%3}, [%4];" \
        : "=r"((r)[0]), "=r"((r)[1]), "=r"((r)[2]), "=r"((r)[3]) : "r"(addr))

#define MMA16816(c, a, b0, b1) \
    asm volatile("mma.sync.aligned.m16n8k16.row.col.f32.bf16.bf16.f32 " \
        "{%0,%1,%2,%3}, {%4,%5,%6,%7}, {%8,%9}, {%0,%1,%2,%3};" \
        : "+f"((c)[0]), "+f"((c)[1]), "+f"((c)[2]), "+f"((c)[3]) \
        : "r"((a)[0]), "r"((a)[1]), "r"((a)[2]), "r"((a)[3]), \
          "r"(b0), "r"(b1))

// ============================================================================
// Prep 1: elementwise fp32 -> bf16 of events and contexts (no concatenation)
// ============================================================================
__global__ __launch_bounds__(256) void conv_kernel(
    const float* __restrict__ events, const float* __restrict__ contexts) {
    const int r = blockIdx.x;                 // 0..EV_ROWS+CX_ROWS-1
    const float* src;
    __nv_bfloat162* dst;
    if (r < EV_ROWS) {
        src = events + (size_t)r * HIDDEN;
        dst = (__nv_bfloat162*)(g_ev + (size_t)r * HIDDEN);
    } else {
        const int rc = r - EV_ROWS;
        src = contexts + (size_t)rc * HIDDEN;
        dst = (__nv_bfloat162*)(g_cx + (size_t)rc * HIDDEN);
    }
    const int t = threadIdx.x;                // 256 threads x float4 = 1024
    float4 v = ((const float4*)src)[t];
    dst[t * 2 + 0] = __floats2bfloat162_rn(v.x, v.y);
    dst[t * 2 + 1] = __floats2bfloat162_rn(v.z, v.w);
}

// ============================================================================
// Prep 2: transposed bf16 weights
//   g_Wd [g][k] = (k<2048 ? Wz[k][g] : 0) - Wqz[k][g]   (k<3072)
//   g_Wzl[g][k] = Wv[k][g]                              (k<2048)
//   g_Wql[g][k] = Wqv[k][g]                             (k<3072)
// ============================================================================
__global__ void transpose_w_kernel(
    const float* __restrict__ Wz, const float* __restrict__ Wqz,
    const float* __restrict__ Wv, const float* __restrict__ Wqv) {
    __shared__ float tile[32][33];
    const int which = blockIdx.z;            // 0=d, 1=zl, 2=ql
    const int k0 = blockIdx.x * 32, g0 = blockIdx.y * 32;
    if (which == 1 && k0 >= KZ) return;
    const int tx = threadIdx.x, ty = threadIdx.y;
    for (int i = ty; i < 32; i += 8) {
        const int k = k0 + i;
        float v;
        if (which == 0)
            v = ((k < KZ) ? Wz[(size_t)k * GCOLS + g0 + tx] : 0.f)
                - Wqz[(size_t)k * GCOLS + g0 + tx];
        else if (which == 1)
            v = Wv[(size_t)k * GCOLS + g0 + tx];
        else
            v = Wqv[(size_t)k * GCOLS + g0 + tx];
        tile[i][tx] = v;
    }
    __syncthreads();
    for (int i = ty; i < 32; i += 8) {
        const __nv_bfloat16 b = __float2bfloat16(tile[tx][i]);
        if (which == 0)      g_Wd [(size_t)(g0 + i) * KQ + k0 + tx] = b;
        else if (which == 1) g_Wzl[(size_t)(g0 + i) * KZ + k0 + tx] = b;
        else                 g_Wql[(size_t)(g0 + i) * KQ + k0 + tx] = b;
    }
}

// ============================================================================
// No-op kernel keeps gemm_kl_kernel at ncu capture slot 5
// ============================================================================
__global__ void dummy_kernel() {}

// ============================================================================
// Fused triple-GEMM + KL epilogue (mma.sync bf16).
// grid (16 g-blocks, 256 m-tiles), 128 threads = 4 warps (1/SMSP), 2 CTAs/SM.
// A loaded directly from g_ev/g_cx per k-segment ([e_s|e_{s+1}] contiguous).
// R13 load schedule: single early burst per kt, one commit group.
// ============================================================================
__global__ __launch_bounds__(128, 2) void gemm_kl_kernel(
    const float* __restrict__ bz, const float* __restrict__ bqz,
    const float* __restrict__ bv, const float* __restrict__ bqv) {
    extern __shared__ char dsm[];
    const uint32_t raw = smem_to_u32(dsm);
    const uint32_t sb = (raw + 1023u) & ~1023u;
    char* smc = dsm + (sb - raw);
    const int tid = threadIdx.x;
    const int lane = tid & 31;
    const int wid = tid >> 5;              // 0..3 == SMSP
    const int nb0 = blockIdx.x * BG;
    const int m0 = blockIdx.y * BM;

    float* sBD = (float*)(smc + OFF_BIAS);        // 64
    float* sBZL = sBD + 64;                       // 64
    float* sBQL = sBZL + 64;                      // 64
    if (tid < 64) {
        sBD[tid]  = bz[nb0 + tid] - bqz[nb0 + tid];
        sBZL[tid] = bv[nb0 + tid];
        sBQL[tid] = bqv[nb0 + tid];
    }

    // ---- per-lane ldmatrix address components (xor swizzle) ----
    const int wn = wid;              // 4 warps along N (16 cols each)
    const uint32_t aswz = (uint32_t)(lane & 7) * 16u;
    const uint32_t acb = (uint32_t)(lane >> 4) * 16u;
    uint32_t aoff[4];
#pragma unroll
    for (int p = 0; p < 4; p++)
        aoff[p] = (uint32_t)(p * 16 + (lane & 15)) * 128u;
    const int brr = wn * 16 + ((lane >> 4) << 3) + (lane & 7);
    const uint32_t boff = (uint32_t)brr * 128u;
    const uint32_t bswz = (uint32_t)(lane & 7) * 16u;
    const uint32_t bcb = (uint32_t)((lane >> 3) & 1) * 16u;

    // ---- accumulators ----
    float accD[4][2][4], accZL[4][2][4], accQL[4][2][4];
#pragma unroll
    for (int p = 0; p < 4; p++)
#pragma unroll
        for (int h = 0; h < 2; h++)
#pragma unroll
            for (int c = 0; c < 4; c++) {
                accD[p][h][c] = 0.f; accZL[p][h][c] = 0.f; accQL[p][h][c] = 0.f;
            }

    // ---- lean loader addressing: row0 = tid>>3 (+16 per j), cb fixed ----
    const int row0 = tid >> 3;
    const int cb16 = (tid & 7) * 16;
    const uint32_t dst0 = (uint32_t)(row0 * 128 + cb16) ^ ((uint32_t)(row0 & 7) * 16u);
    const int r0 = m0 + row0;
    const int ii = r0 >> 2, ss = r0 & 3;
    const char* pA = (const char*)(g_ev + ((size_t)ii * 5 + ss) * HIDDEN) + cb16;
    const char* pC = (const char*)(g_cx + ((size_t)ii * 4 + ss) * HIDDEN) + cb16 - 4096;
    const char* pBd  = (const char*)(g_Wd  + (size_t)(nb0 + row0) * KQ) + cb16;
    const char* pBql = (const char*)(g_Wql + (size_t)(nb0 + row0) * KQ) + cb16;
    const char* pBzl = (const char*)(g_Wzl + (size_t)(nb0 + row0) * KZ) + cb16;

    // Single burst per kt (R13 schedule): all sections + one commit.
#define LOAD_STAGE(kt) do { \
        const uint32_t _sB = sb + (uint32_t)((kt) % 3) * STAGE_BYTES; \
        const int _kb = (kt) * 128; \
        const char* _a = ((kt) < NKT_Z) ? (pA + _kb) : (pC + _kb); \
        const int _as = ((kt) < NKT_Z) ? 40960 : 32768; \
        _Pragma("unroll") \
        for (int _j = 0; _j < 4; _j++) cp16(_sB + dst0 + _j * 2048u, _a + _j * _as); \
        _Pragma("unroll") \
        for (int _j = 0; _j < 4; _j++) cp16(_sB + 8192u + dst0 + _j * 2048u, pBd + _kb + _j * 98304); \
        _Pragma("unroll") \
        for (int _j = 0; _j < 4; _j++) cp16(_sB + 16384u + dst0 + _j * 2048u, pBql + _kb + _j * 98304); \
        if ((kt) < NKT_Z) { \
            _Pragma("unroll") \
            for (int _j = 0; _j < 4; _j++) cp16(_sB + 24576u + dst0 + _j * 2048u, pBzl + _kb + _j * 65536); \
        } \
        CP_COMMIT(); \
    } while (0)

    // ---- fragment double buffers ----
    uint32_t aF[2][4][4], fdF[2][4], fqlF[2][4], fzlF[2][4];

#define LDFRAG(buf, ks, stA, full) do { \
        const uint32_t _ka = (((uint32_t)(ks) * 32u + acb) ^ aswz); \
        const uint32_t _kb = (((uint32_t)(ks) * 32u + bcb) ^ bswz); \
        LDSM4(aF[buf][0], (stA) + aoff[0] + _ka); \
        LDSM4(aF[buf][1], (stA) + aoff[1] + _ka); \
        LDSM4(aF[buf][2], (stA) + aoff[2] + _ka); \
        LDSM4(aF[buf][3], (stA) + aoff[3] + _ka); \
        LDSM4(fdF[buf],  (stA) + 8192u + boff + _kb); \
        LDSM4(fqlF[buf], (stA) + 16384u + boff + _kb); \
        if (full) LDSM4(fzlF[buf], (stA) + 24576u + boff + _kb); \
    } while (0)

#define DOMMA(buf, full) do { \
        _Pragma("unroll") \
        for (int _p = 0; _p < 4; _p++) { \
            _Pragma("unroll") \
            for (int _h = 0; _h < 2; _h++) { \
                MMA16816(accD[_p][_h],  aF[buf][_p], fdF[buf][2*_h],  fdF[buf][2*_h+1]); \
                MMA16816(accQL[_p][_h], aF[buf][_p], fqlF[buf][2*_h], fqlF[buf][2*_h+1]); \
            } \
        } \
        if (full) { \
            _Pragma("unroll") \
            for (int _p = 0; _p < 4; _p++) { \
                _Pragma("unroll") \
                for (int _h = 0; _h < 2; _h++) \
                    MMA16816(accZL[_p][_h], aF[buf][_p], fzlF[buf][2*_h], fzlF[buf][2*_h+1]); \
            } \
        } \
    } while (0)

    // ---- prologue: 2 stages in flight, prefetch ks0 of stage 0 ----
    LOAD_STAGE(0);
    LOAD_STAGE(1);
    asm volatile("cp.async.wait_group 1;" ::: "memory");
    __syncthreads();
    LDFRAG(0, 0, sb, true);

    for (int kt = 0; kt < NKT; kt++) {
        const uint32_t stA = sb + (uint32_t)(kt % 3) * STAGE_BYTES;
        const bool full = (kt < NKT_Z);
        // buf0 already holds ks0 fragments (prefetched)
        LDFRAG(1, 1, stA, full);
        if (kt + 2 < NKT) LOAD_STAGE(kt + 2);
        DOMMA(0, full);
        LDFRAG(0, 2, stA, full);
        DOMMA(1, full);
        LDFRAG(1, 3, stA, full);
        DOMMA(0, full);
        if (kt < NKT - 1) {
            // stage kt+1 fully resident after this wait+barrier
            if (kt + 2 < NKT) { asm volatile("cp.async.wait_group 1;" ::: "memory"); }
            else              { asm volatile("cp.async.wait_group 0;" ::: "memory"); }
            __syncthreads();
            const uint32_t stN = sb + (uint32_t)((kt + 1) % 3) * STAGE_BYTES;
            const bool fulln = (kt + 1 < NKT_Z);
            LDFRAG(0, 0, stN, fulln);     // prefetch next kt's ks0
        }
        DOMMA(1, full);
    }

    // ---- fused KL epilogue: identical fragment layouts -> no shuffles ----
    float acckl = 0.f;
#pragma unroll
    for (int p = 0; p < 4; p++) {
#pragma unroll
        for (int h = 0; h < 2; h++) {
            const int col = wn * 16 + h * 8 + (lane & 3) * 2;
            const float bd0 = sBD[col], bd1 = sBD[col + 1];
            const float bl0 = sBZL[col], bl1 = sBZL[col + 1];
            const float bq0 = sBQL[col], bq1 = sBQL[col + 1];
#pragma unroll
            for (int rr = 0; rr < 2; rr++) {
                const float d0 = accD[p][h][2 * rr] + bd0;
                const float d1 = accD[p][h][2 * rr + 1] + bd1;
                const float zl0 = accZL[p][h][2 * rr] + bl0;
                const float zl1 = accZL[p][h][2 * rr + 1] + bl1;
                const float ql0 = accQL[p][h][2 * rr] + bq0;
                const float ql1 = accQL[p][h][2 * rr + 1] + bq1;
                acckl += ql0 - zl0 + (expf(zl0) + d0 * d0) * expf(-ql0) - 1.f;
                acckl += ql1 - zl1 + (expf(zl1) + d1 * d1) * expf(-ql1) - 1.f;
            }
        }
    }

    // deterministic reduction over 4 warps
#pragma unroll
    for (int s = 16; s > 0; s >>= 1)
        acckl += __shfl_down_sync(0xFFFFFFFFu, acckl, s);
    float* red = (float*)(smc + OFF_RED);
    if (lane == 0) red[wid] = acckl;
    __syncthreads();
    if (tid == 0) {
        float s = 0.f;
        for (int w = 0; w < 4; w++) s += red[w];
        g_kl_partial[blockIdx.y * 16 + blockIdx.x] = s;
    }
}

// ============================================================================
// Small losses: 32 blocks x 128 threads, one batch element each
// ============================================================================
__global__ __launch_bounds__(128) void small_loss_kernel(
    const float* __restrict__ ps, const float* __restrict__ pt,
    const float* __restrict__ pc, const int* __restrict__ labels,
    const int* __restrict__ scene, const int* __restrict__ thr) {
    __shared__ float red[128];
    const int b = blockIdx.x * 128 + threadIdx.x;    // < 4096
    float wce = 0.f, wsum = 0.f, tsum = 0.f, vsum = 0.f;
    {
        const int lab = labels[b];
        const int s = scene[b], t = thr[b];
        const bool l5 = (lab == 5), l2 = (lab == 2), l3 = (lab == 3);
        const bool le = !(l5 | l2 | l3);
        const int nv = l5 ? 3 : (l2 ? 1 : (l3 ? 2 : 3));
        const int last = nv - 1;
        const float* psb = ps + (size_t)b * 6;
        const float* ptb = pt + (size_t)b * 6;
        const float* pcb = pc + (size_t)b * 6;
        #pragma unroll
        for (int slot = 0; slot < 3; slot++) {
            if (slot >= nv) break;
            int chain = l5 ? 1 : (l2 ? 0 : (l3 ? (slot == 0 ? 1 : 0)
                                               : (slot == 2 ? 0 : 1)));
            int ps_col = (!l5 && slot == last) ? s : 0;
            int pt_row = (l3 && slot == 1) ? (t == 1 ? 0 : 1) : slot;
            int pt_col = (l2 && slot == 0) ? t : ((le && slot == 2) ? t : 0);
            int pcs_col = l5 ? 1 : (slot == last ? 0 : 1);
            float PS = psb[slot * 2 + ps_col];
            float PT = ptb[pt_row * 2 + pt_col];
            float PCS = pcb[slot * 2 + pcs_col];
            float a0 = pcb[slot * 2 + 0], a1 = pcb[slot * 2 + 1];
            float mx = fmaxf(a0, a1);
            float lse = mx + logf(expf(a0 - mx) + expf(a1 - mx));
            float logp = (chain == 0 ? a0 : a1) - lse;
            float w = (chain == 0) ? 0.6f : 0.4f;
            wce += -w * logp;
            wsum += w;
            float lsig = fminf(PCS, 0.f) - log1pf(expf(-fabsf(PCS)));
            tsum += fabsf(logf(PS) + logf(PT) - lsig);
            vsum += 1.f;
        }
    }
    const int tid = threadIdx.x;
    float vals[4] = {wce, wsum, tsum, vsum};
    for (int v = 0; v < 4; v++) {
        red[tid] = vals[v];
        __syncthreads();
        for (int sft = 64; sft > 0; sft >>= 1) {
            if (tid < sft) red[tid] += red[tid + sft];
            __syncthreads();
        }
        if (tid == 0) g_small_partial[blockIdx.x * 4 + v] = red[0];
        __syncthreads();
    }
}

// ============================================================================
// Final combine
// ============================================================================
__global__ __launch_bounds__(1024) void combine_kernel(float* __restrict__ out) {
    __shared__ float red[1024];
    float s = 0.f;
    for (int i = threadIdx.x; i < 4096; i += 1024) s += g_kl_partial[i];
    red[threadIdx.x] = s;
    __syncthreads();
    for (int sft = 512; sft > 0; sft >>= 1) {
        if (threadIdx.x < sft) red[threadIdx.x] += red[threadIdx.x + sft];
        __syncthreads();
    }
    if (threadIdx.x == 0) {
        float sm[4] = {0.f, 0.f, 0.f, 0.f};
        for (int bi = 0; bi < SL_BLOCKS; bi++)
            for (int v = 0; v < 4; v++) sm[v] += g_small_partial[bi * 4 + v];
        const float kl_loss = 0.5f * red[0] / (float)M_TOTAL;
        out[0] = sm[0] / sm[1] + kl_loss + sm[2] / sm[3];
    }
}

// ============================================================================
// kernel_launch
// ============================================================================
extern "C" void kernel_launch(void* const* d_in, const int* in_sizes, int n_in,
                              void* d_out, int out_size) {
    const float* events   = (const float*)d_in[0];
    const float* contexts = (const float*)d_in[1];
    const float* ps       = (const float*)d_in[2];
    const float* pt       = (const float*)d_in[3];
    const float* pc       = (const float*)d_in[4];
    const int*   labels   = (const int*)d_in[5];
    const int*   scene    = (const int*)d_in[6];
    const int*   thr      = (const int*)d_in[7];
    const float* Wz  = (const float*)d_in[8];
    const float* bz  = (const float*)d_in[9];
    const float* Wv  = (const float*)d_in[10];
    const float* bv  = (const float*)d_in[11];
    const float* Wqz = (const float*)d_in[12];
    const float* bqz = (const float*)d_in[13];
    const float* Wqv = (const float*)d_in[14];
    const float* bqv = (const float*)d_in[15];
    float* out = (float*)d_out;

    cudaFuncSetAttribute(gemm_kl_kernel,
                         cudaFuncAttributeMaxDynamicSharedMemorySize, SMEM_REQ);

    conv_kernel<<<EV_ROWS + CX_ROWS, 256>>>(events, contexts);                   // my #0
    transpose_w_kernel<<<dim3(KQ / 32, GCOLS / 32, 3), dim3(32, 8)>>>(Wz, Wqz, Wv, Wqv); // #1
    dummy_kernel<<<1, 32>>>();                                                   // #2
    gemm_kl_kernel<<<dim3(GCOLS / BG, M_TOTAL / BM), 128, SMEM_REQ>>>(bz, bqz, bv, bqv); // #3 <- ncu slot 5
    small_loss_kernel<<<SL_BLOCKS, 128>>>(ps, pt, pc, labels, scene, thr);       // #4
    combine_kernel<<<1, 1024>>>(out);                                            // #5
}